// round 5
// baseline (speedup 1.0000x reference)
#include <cuda_runtime.h>
#include <mma.h>
#include <cstdint>

using namespace nvcuda;

#define BATCH   4096
#define INDIM   1024
#define OUTDIM  1024
#define NNZ     52224

#define BM 128
#define BN 128
#define BK 32
#define NCHUNK (INDIM / BK)      // 32
#define GT 512                   // 16 warps: 4 (M) x 4 (N), each computes 32x32
#define LDS_PAD 36               // smem row stride in floats (144 B, 16B aligned)
#define LDS_PAD_B (LDS_PAD * 4)  // 144 bytes

// Device scratch (allocation-free rule: __device__ globals)
__device__ float g_W[OUTDIM * INDIM];   // dense scattered W, K-major, tf32-rounded (4 MB)
__device__ float g_A[BATCH * INDIM];    // input, tf32-rounded (16 MB)

// ---------------- helpers ----------------

__device__ __forceinline__ uint32_t smem_u32(const void* p) {
    uint32_t a;
    asm("{ .reg .u64 t; cvta.to.shared.u64 t, %1; cvt.u32.u64 %0, t; }" : "=r"(a) : "l"(p));
    return a;
}
__device__ __forceinline__ float tf32_rna(float x) {
    uint32_t r;
    asm("cvt.rna.tf32.f32 %0, %1;" : "=r"(r) : "f"(x));
    return __uint_as_float(r);
}
#define CP_ASYNC16(saddr, gptr) \
    asm volatile("cp.async.cg.shared.global [%0], [%1], 16;" :: "r"(saddr), "l"(gptr))
#define CP_COMMIT() asm volatile("cp.async.commit_group;" ::: "memory")

// ---------------- prep kernels ----------------

__global__ void k_wzero() {
    int i = blockIdx.x * blockDim.x + threadIdx.x;     // 262144 float4
    ((float4*)g_W)[i] = make_float4(0.f, 0.f, 0.f, 0.f);
}
__global__ void k_wscatter(const int* __restrict__ ind_in,
                           const int* __restrict__ ind_out,
                           const float* __restrict__ weight) {
    int k = blockIdx.x * blockDim.x + threadIdx.x;
    if (k < NNZ)
        atomicAdd(&g_W[ind_out[k] * INDIM + ind_in[k]], tf32_rna(weight[k]));
}
__global__ void k_acvt(const float* __restrict__ input) {
    int i = blockIdx.x * blockDim.x + threadIdx.x;     // 1M float4
    float4 v = ((const float4*)input)[i];
    ((float4*)g_A)[i] = make_float4(tf32_rna(v.x), tf32_rna(v.y),
                                    tf32_rna(v.z), tf32_rna(v.w));
}

// ---------------- main: tf32 wmma GEMM   out = A @ W^T + bias ----------------
//
// smem layout (dynamic, 73728 B):
//   bufA[0]@0        128x36 floats (18432 B)
//   bufB[0]@18432    128x36 floats
//   bufA[1]@36864
//   bufB[1]@55296
// epilogue reuses smem from 0 as float stage[128][132] (67584 B)
#define OFF_A0 0
#define OFF_B0 18432
#define OFF_A1 36864
#define OFF_B1 55296
#define SMEM_TOTAL 73728

__global__ __launch_bounds__(GT, 2)
void k_gemm(const float* __restrict__ bias, float* __restrict__ out) {
    extern __shared__ __align__(128) char smem[];
    const uint32_t sb = smem_u32(smem);
    const int tid = threadIdx.x;
    const int wid = tid >> 5;
    const int m0 = (blockIdx.x & 31) * BM;
    const int n0 = (blockIdx.x >> 5) * BN;
    const int warp_m = (wid >> 2) * 32;    // warp row base within tile
    const int warp_n = (wid & 3)  * 32;    // warp col base within tile

    const int offA[2] = {OFF_A0, OFF_A1};
    const int offB[2] = {OFF_B0, OFF_B1};

    // cp.async per-thread addresses: 1024 float4 per tile, 512 threads -> 2 each
    // id = it*512 + tid: row = id>>3 (0..127), c4 = id&7
    auto load_chunk = [&](int c, int buf) {
        const int k0 = c * BK;
        #pragma unroll
        for (int it = 0; it < 2; ++it) {
            int id  = it * GT + tid;
            int row = id >> 3, c4 = id & 7;
            const float* ga = g_A + (size_t)(m0 + row) * INDIM + k0 + c4 * 4;
            CP_ASYNC16(sb + offA[buf] + row * LDS_PAD_B + c4 * 16, ga);
        }
        #pragma unroll
        for (int it = 0; it < 2; ++it) {
            int id  = it * GT + tid;
            int row = id >> 3, c4 = id & 7;
            const float* gb = g_W + (size_t)(n0 + row) * INDIM + k0 + c4 * 4;
            CP_ASYNC16(sb + offB[buf] + row * LDS_PAD_B + c4 * 16, gb);
        }
        CP_COMMIT();
    };

    wmma::fragment<wmma::accumulator, 16, 16, 8, float> acc[2][2];
    #pragma unroll
    for (int i = 0; i < 2; ++i)
        #pragma unroll
        for (int j = 0; j < 2; ++j)
            wmma::fill_fragment(acc[i][j], 0.0f);

    load_chunk(0, 0);

    for (int c = 0; c < NCHUNK; ++c) {
        const int buf = c & 1;
        if (c + 1 < NCHUNK) {
            load_chunk(c + 1, buf ^ 1);
            asm volatile("cp.async.wait_group 1;" ::: "memory");
        } else {
            asm volatile("cp.async.wait_group 0;" ::: "memory");
        }
        __syncthreads();

        const float* sA = (const float*)(smem + offA[buf]);
        const float* sB = (const float*)(smem + offB[buf]);

        #pragma unroll
        for (int ks = 0; ks < BK / 8; ++ks) {
            wmma::fragment<wmma::matrix_a, 16, 16, 8, wmma::precision::tf32, wmma::row_major> aF[2];
            wmma::fragment<wmma::matrix_b, 16, 16, 8, wmma::precision::tf32, wmma::col_major> bF[2];
            #pragma unroll
            for (int i = 0; i < 2; ++i)
                wmma::load_matrix_sync(aF[i], sA + (warp_m + i * 16) * LDS_PAD + ks * 8, LDS_PAD);
            #pragma unroll
            for (int j = 0; j < 2; ++j)
                wmma::load_matrix_sync(bF[j], sB + (warp_n + j * 16) * LDS_PAD + ks * 8, LDS_PAD);
            #pragma unroll
            for (int i = 0; i < 2; ++i)
                #pragma unroll
                for (int j = 0; j < 2; ++j)
                    wmma::mma_sync(acc[i][j], aF[i], bF[j], acc[i][j]);
        }
        __syncthreads();
    }

    // Epilogue: frags -> smem stage (ld=132) -> +bias, coalesced float4 stores
    float* stage = (float*)smem;
    const int SLD = 132;
    #pragma unroll
    for (int i = 0; i < 2; ++i)
        #pragma unroll
        for (int j = 0; j < 2; ++j)
            wmma::store_matrix_sync(stage + (warp_m + i * 16) * SLD + warp_n + j * 16,
                                    acc[i][j], SLD, wmma::mem_row_major);
    __syncthreads();

    // 128x128 floats = 4096 float4, 512 threads -> 8 each
    #pragma unroll
    for (int it = 0; it < 8; ++it) {
        int id  = it * GT + tid;
        int row = id >> 5, c4 = id & 31;                 // 32 float4 per row
        float4 v = *(const float4*)(stage + row * SLD + c4 * 4);
        float4 bz = *(const float4*)(bias + n0 + c4 * 4);
        v.x += bz.x; v.y += bz.y; v.z += bz.z; v.w += bz.w;
        *(float4*)(out + (size_t)(m0 + row) * OUTDIM + n0 + c4 * 4) = v;
    }
}

// ---------------- launch ----------------

extern "C" void kernel_launch(void* const* d_in, const int* in_sizes, int n_in,
                              void* d_out, int out_size) {
    const float* input   = (const float*)d_in[0];   // [4096,1024] f32
    const float* weight  = (const float*)d_in[1];   // [52224]     f32
    const float* bias    = (const float*)d_in[2];   // [1024]      f32
    const int*   ind_in  = (const int*)  d_in[3];   // [52224]     i32
    const int*   ind_out = (const int*)  d_in[4];   // [52224]     i32
    float*       out     = (float*)d_out;           // [4096,1024] f32

    cudaFuncSetAttribute(k_gemm, cudaFuncAttributeMaxDynamicSharedMemorySize, SMEM_TOTAL);

    k_wzero<<<1024, 256>>>();                                  // 4 MB zero
    k_wscatter<<<(NNZ + 255) / 256, 256>>>(ind_in, ind_out, weight);
    k_acvt<<<4096, 256>>>(input);                              // input -> tf32-rounded g_A
    k_gemm<<<(BATCH / BM) * (OUTDIM / BN), GT, SMEM_TOTAL>>>(bias, out);
}

// round 8
// speedup vs baseline: 2.6303x; 2.6303x over previous
#include <cuda_runtime.h>
#include <cuda_fp16.h>
#include <cstdint>

#define BATCH   4096
#define INDIM   1024
#define OUTDIM  1024
#define NNZ     52224

#define ROWS    64           // batch rows per CTA (2 per lane, fp16x2-packed)
#define THREADS 1024         // 32 warps
#define CPW     16           // columns per warp (512 cols per CTA / 32 warps)
#define WSTRIDE 33           // words per input column (32 row-pairs + 1 pad)
#define CAP     128          // max entries per output column (mean ~51)
#define CAP2    136          // list stride: CAP + 2 quads (pad + prefetch)
#define SLD     516          // epilogue stage row stride (floats; mult of 4 -> 16B-aligned rows)

// Device scratch (allocation-free rule: __device__ globals)
__device__ int g_len[OUTDIM];
__device__ int g_lq[OUTDIM];                          // quad count per column
__device__ __align__(16) unsigned g_ii[OUTDIM * CAP2];// BYTE offsets: ind_in*WSTRIDE*4
__device__ __align__(16) float    g_w [OUTDIM * CAP2];

__device__ __forceinline__ unsigned h2_as_u32(__half2 h) {
    union { __half2 h; unsigned u; } cvt;
    cvt.h = h;
    return cvt.u;
}

// ---------------- preprocessing: bucket NNZ by output column ----------------

__global__ void k_zero() {
    int j = blockIdx.x * blockDim.x + threadIdx.x;
    if (j < OUTDIM) g_len[j] = 0;
}

__global__ void k_fill(const int* __restrict__ ind_in,
                       const int* __restrict__ ind_out,
                       const float* __restrict__ weight) {
    int k = blockIdx.x * blockDim.x + threadIdx.x;
    if (k < NNZ) {
        int j = ind_out[k];
        int p = atomicAdd(&g_len[j], 1);
        if (p < CAP) {
            g_ii[j * CAP2 + p] = (unsigned)(ind_in[k] * (WSTRIDE * 4));
            g_w [j * CAP2 + p] = weight[k];
        }
    }
}

// Pad each list to a multiple of 4 PLUS one extra quad of zeros so the main
// loop can prefetch quad p+1 unconditionally.
__global__ void k_pad() {
    int j = blockIdx.x * blockDim.x + threadIdx.x;
    if (j < OUTDIM) {
        int n  = min(g_len[j], CAP);
        int n4 = (n + 3) & ~3;
        for (int p = n; p < n4 + 4; ++p) {
            g_ii[j * CAP2 + p] = 0u;
            g_w [j * CAP2 + p] = 0.0f;
        }
        g_lq[j] = n4 >> 2;
    }
}

// ---------------- main kernel ----------------
//
// CTA = 64 batch rows x 512 output cols. Input tile in smem as fp16x2:
// word[col*33 + l] packs rows (2l, 2l+1). One conflict-free LDS.32 per entry
// gathers 64 rows (2 per lane) -> half the L1 wavefronts of the fp32 design.
// Entry quads (LDG.128 ii + w) are prefetched one iteration ahead to hide L2
// latency. Epilogue transposes through smem for coalesced float4 stores.

__global__ __launch_bounds__(THREADS, 1)
void k_main(const float* __restrict__ input,
            const float* __restrict__ bias,
            float* __restrict__ out) {
    extern __shared__ __align__(16) char smem[];
    unsigned* sw = (unsigned*)smem;
    const int tid      = threadIdx.x;
    const int tile     = blockIdx.x >> 1;
    const int ch       = blockIdx.x & 1;          // column half: 0 or 1
    const int base_row = tile * ROWS;
    const int jbase    = ch * (OUTDIM / 2);

    // ---- fill: pack rows (2rp, 2rp+1) as fp16x2, word[col*33 + rp] ----
    #pragma unroll
    for (int it = 0; it < 8; ++it) {
        int idx = it * THREADS + tid;             // 8192 = 32 row-pairs x 256 col-quads
        int rp  = idx >> 8;                       // 0..31
        int c4  = idx & 255;
        const float4 a = *(const float4*)(input + (size_t)(base_row + 2 * rp)     * INDIM + c4 * 4);
        const float4 b = *(const float4*)(input + (size_t)(base_row + 2 * rp + 1) * INDIM + c4 * 4);
        sw[(4 * c4 + 0) * WSTRIDE + rp] = h2_as_u32(__floats2half2_rn(a.x, b.x));
        sw[(4 * c4 + 1) * WSTRIDE + rp] = h2_as_u32(__floats2half2_rn(a.y, b.y));
        sw[(4 * c4 + 2) * WSTRIDE + rp] = h2_as_u32(__floats2half2_rn(a.z, b.z));
        sw[(4 * c4 + 3) * WSTRIDE + rp] = h2_as_u32(__floats2half2_rn(a.w, b.w));
    }
    __syncthreads();

    const int warp = tid >> 5;
    const int lane = tid & 31;
    const char* lane_base = (const char*)smem + lane * 4;

    float accE[CPW], accO[CPW];                   // rows 2*lane / 2*lane+1

    #pragma unroll
    for (int c = 0; c < CPW; ++c) {
        const int j = jbase + warp * CPW + c;     // global output column
        const int L = g_lq[j];
        const uint4*  ip = (const uint4* )(g_ii + j * CAP2);
        const float4* wp = (const float4*)(g_w  + j * CAP2);
        uint4  ii = ip[0];
        float4 ww = wp[0];
        float a0 = 0.f, a1 = 0.f, b0 = 0.f, b1 = 0.f;
        for (int p = 0; p < L; ++p) {
            uint4  iin = ip[p + 1];               // prefetch next quad (padded-safe)
            float4 wwn = wp[p + 1];
            float2 f;
            f = __half22float2(*(const __half2*)(lane_base + ii.x));
            a0 += f.x * ww.x;  a1 += f.y * ww.x;
            f = __half22float2(*(const __half2*)(lane_base + ii.y));
            b0 += f.x * ww.y;  b1 += f.y * ww.y;
            f = __half22float2(*(const __half2*)(lane_base + ii.z));
            a0 += f.x * ww.z;  a1 += f.y * ww.z;
            f = __half22float2(*(const __half2*)(lane_base + ii.w));
            b0 += f.x * ww.w;  b1 += f.y * ww.w;
            ii = iin; ww = wwn;
        }
        accE[c] = a0 + b0;
        accO[c] = a1 + b1;
    }

    // ---- epilogue: stage[row][lcol] (stride 516), then coalesced stores ----
    __syncthreads();                              // all gathers done; reuse smem
    float* st = (float*)smem;
    #pragma unroll
    for (int c = 0; c < CPW; ++c) {
        int lcol = warp * CPW + c;                // 0..511
        st[(2 * lane)     * SLD + lcol] = accE[c];
        st[(2 * lane + 1) * SLD + lcol] = accO[c];
    }
    __syncthreads();

    #pragma unroll
    for (int it = 0; it < 8; ++it) {
        int idx = it * THREADS + tid;             // 8192 float4 = 64 rows x 128
        int row = idx >> 7;
        int c4  = idx & 127;
        float4 v  = *(const float4*)(st + row * SLD + c4 * 4);
        float4 bz = *(const float4*)(bias + jbase + c4 * 4);
        v.x += bz.x; v.y += bz.y; v.z += bz.z; v.w += bz.w;
        *(float4*)(out + (size_t)(base_row + row) * OUTDIM + jbase + c4 * 4) = v;
    }
}

// ---------------- launch ----------------

extern "C" void kernel_launch(void* const* d_in, const int* in_sizes, int n_in,
                              void* d_out, int out_size) {
    const float* input   = (const float*)d_in[0];   // [4096,1024] f32
    const float* weight  = (const float*)d_in[1];   // [52224]     f32
    const float* bias    = (const float*)d_in[2];   // [1024]      f32
    const int*   ind_in  = (const int*)  d_in[3];   // [52224]     i32
    const int*   ind_out = (const int*)  d_in[4];   // [52224]     i32
    float*       out     = (float*)d_out;           // [4096,1024] f32

    const int smem_bytes = INDIM * WSTRIDE * 4;     // 135168 (stage 64x516x4=132096 fits)
    cudaFuncSetAttribute(k_main, cudaFuncAttributeMaxDynamicSharedMemorySize, smem_bytes);

    k_zero<<<(OUTDIM + 255) / 256, 256>>>();
    k_fill<<<(NNZ + 255) / 256, 256>>>(ind_in, ind_out, weight);
    k_pad <<<(OUTDIM + 255) / 256, 256>>>();
    k_main<<<(BATCH / ROWS) * 2, THREADS, smem_bytes>>>(input, bias, out);
}